// round 1
// baseline (speedup 1.0000x reference)
#include <cuda_runtime.h>

#define B_    16
#define T_    256
#define MEL_  1024
#define D_    512
#define H_    8
#define L_    4
#define INTER_ 2048
#define OUT_  80

// ---------------- scratch (static device globals: no allocations) ----------
__device__ float g_x  [(size_t)B_*MEL_*D_];
__device__ float g_y  [(size_t)B_*MEL_*D_];
__device__ float g_ctx[(size_t)B_*MEL_*D_];
__device__ float g_qkv[(size_t)B_*MEL_*3*D_];
__device__ float g_h  [(size_t)B_*MEL_*INTER_];
__device__ int   g_idx[B_*MEL_];

// ---------------- embedding + positional encoding --------------------------
// x[b,t,:] = 2*emb[tok[b,t],:] + pos[b,:]   (reference indexes pos by BATCH)
__global__ void embed_k(const int* __restrict__ tokens,
                        const float* __restrict__ emb,
                        float* __restrict__ x)
{
    int row = blockIdx.x;            // b*T + t
    int b   = row >> 8;              // T_=256
    int tok = tokens[row];
    int tid = threadIdx.x;           // 128 threads, float4 each
    float4 e = ((const float4*)(emb + (size_t)tok * D_))[tid];
    int d0 = tid * 4;
    const float c = 9.210340371976184f / (float)D_;   // ln(10000)/D
    float den0 = __expf(-(float)(d0)     * c);
    float den1 = __expf(-(float)(d0 + 2) * c);
    float a0 = (float)b * den0, a1 = (float)b * den1;
    float4 o;
    o.x = 2.f * e.x + sinf(a0);
    o.y = 2.f * e.y + cosf(a0);
    o.z = 2.f * e.z + sinf(a1);
    o.w = 2.f * e.w + cosf(a1);
    ((float4*)(x + (size_t)row * D_))[tid] = o;
}

// ---------------- generic tiled GEMM  C = op(A) @ W + bias (+R) ------------
// CONV==1: A is [B*S, Din], virtual K dim = 3*Din with SAME zero padding
// TRANS==1: store C[row, col] at out[(b*OUT_+col)*MEL_ + f]  (row = b*MEL_+f)
template<int CONV, bool RELU, bool RESID, bool TRANS>
__global__ __launch_bounds__(256) void gemm_k(
    const float* __restrict__ A, const float* __restrict__ W,
    const float* __restrict__ bias, const float* __restrict__ R,
    float* __restrict__ C, int N, int M, int Kd, int S, int Din)
{
    __shared__ float As[8][132];
    __shared__ float Bs[8][132];
    int tid  = threadIdx.x;
    int rowB = blockIdx.y * 128;
    int colB = blockIdx.x * 128;
    int ty = tid >> 4, tx = tid & 15;

    int ar   = tid >> 1;            // 0..127  (A tile row)
    int akb  = (tid & 1) * 4;       // k-sub 0 or 4
    int arow = rowB + ar;
    int bkt  = tid >> 5;            // 0..7    (W tile k-row)
    int bc   = (tid & 31) * 4;      // 0..124
    int bcol = colB + bc;

    float acc[8][8];
#pragma unroll
    for (int i = 0; i < 8; i++)
#pragma unroll
        for (int j = 0; j < 8; j++) acc[i][j] = 0.f;

    auto loadA = [&](int k0) -> float4 {
        float4 v = make_float4(0.f, 0.f, 0.f, 0.f);
        if (arow < N) {
            if (CONV == 0) {
                v = *(const float4*)(A + (size_t)arow * Kd + k0 + akb);
            } else {
                int bb = arow / S, ss = arow - bb * S;
                int kk = k0 + akb;
                int kc = kk / Din;
                int d  = kk - kc * Din;
                int p  = ss + kc - 1;
                if (p >= 0 && p < S)
                    v = *(const float4*)(A + ((size_t)(bb * S + p)) * Din + d);
            }
        }
        return v;
    };
    auto loadB = [&](int k0) -> float4 {
        float4 v = make_float4(0.f, 0.f, 0.f, 0.f);
        if (bcol < M)
            v = *(const float4*)(W + (size_t)(k0 + bkt) * M + bcol);
        return v;
    };

    float4 aReg = loadA(0);
    float4 bReg = loadB(0);

    for (int k0 = 0; k0 < Kd; k0 += 8) {
        As[akb + 0][ar] = aReg.x;
        As[akb + 1][ar] = aReg.y;
        As[akb + 2][ar] = aReg.z;
        As[akb + 3][ar] = aReg.w;
        *(float4*)&Bs[bkt][bc] = bReg;
        __syncthreads();
        if (k0 + 8 < Kd) { aReg = loadA(k0 + 8); bReg = loadB(k0 + 8); }
#pragma unroll
        for (int kt = 0; kt < 8; kt++) {
            float a[8], b[8];
            *(float4*)&a[0] = *(const float4*)&As[kt][ty * 4];
            *(float4*)&a[4] = *(const float4*)&As[kt][64 + ty * 4];
            *(float4*)&b[0] = *(const float4*)&Bs[kt][tx * 4];
            *(float4*)&b[4] = *(const float4*)&Bs[kt][64 + tx * 4];
#pragma unroll
            for (int i = 0; i < 8; i++)
#pragma unroll
                for (int j = 0; j < 8; j++) acc[i][j] += a[i] * b[j];
        }
        __syncthreads();
    }

#pragma unroll
    for (int i = 0; i < 8; i++) {
        int row = rowB + ((i < 4) ? (ty * 4 + i) : (64 + ty * 4 + i - 4));
        if (row >= N) continue;
#pragma unroll
        for (int j = 0; j < 8; j++) {
            int col = colB + ((j < 4) ? (tx * 4 + j) : (64 + tx * 4 + j - 4));
            if (col >= M) continue;
            float v = acc[i][j] + bias[col];
            if (RESID) v += R[(size_t)row * M + col];
            if (RELU)  v = fmaxf(v, 0.f);
            if (!TRANS) {
                C[(size_t)row * M + col] = v;
            } else {
                int bb = row / MEL_, f = row - bb * MEL_;
                C[((size_t)(bb * OUT_ + col)) * MEL_ + f] = v;
            }
        }
    }
}

// ---------------- fused attention (online softmax, 64x64 tiles) ------------
#define APITCH 68
#define ATTN_SMEM_BYTES ((4 * 64 * APITCH + 64 * 16 + 128) * 4)
__global__ __launch_bounds__(256) void attn_k(const float* __restrict__ qkv,
                                              const int* __restrict__ lens,
                                              float* __restrict__ ctx, int S)
{
    extern __shared__ float sm[];
    float* Qs   = sm;                    // [d][q]  pitch 68
    float* Ks   = Qs + 64 * APITCH;      // [d][k]
    float* Vs   = Ks + 64 * APITCH;      // [k][d]
    float* Ps   = Vs + 64 * APITCH;      // [k][q]
    float* red  = Ps + 64 * APITCH;      // [64][16]
    float* mrow = red + 64 * 16;         // [64]
    float* lrow = mrow + 64;             // [64]

    int tid = threadIdx.x;
    int ty = tid >> 4, tx = tid & 15;
    int bh = blockIdx.y;
    int b = bh >> 3, h = bh & 7;
    int qt = blockIdx.x;
    int len = lens[b];
    const float* base = qkv + ((size_t)b * S) * (3 * D_);

#pragma unroll
    for (int r = 0; r < 16; r++) {
        int e = r * 256 + tid;
        int qq = e >> 6, d = e & 63;
        Qs[d * APITCH + qq] = base[(size_t)(qt * 64 + qq) * (3 * D_) + h * 64 + d];
    }
    if (tid < 64) { mrow[tid] = -3.0e38f; lrow[tid] = 0.f; }
    float o[4][4];
#pragma unroll
    for (int i = 0; i < 4; i++)
#pragma unroll
        for (int j = 0; j < 4; j++) o[i][j] = 0.f;
    __syncthreads();

    int nkt = S >> 6;
    for (int kt = 0; kt < nkt; kt++) {
#pragma unroll
        for (int r = 0; r < 16; r++) {
            int e = r * 256 + tid;
            int kk = e >> 6, d = e & 63;
            size_t g = (size_t)(kt * 64 + kk) * (3 * D_) + h * 64 + d;
            Ks[d * APITCH + kk] = base[g + D_];
            Vs[kk * APITCH + d] = base[g + 2 * D_];
        }
        __syncthreads();

        float s[4][4];
#pragma unroll
        for (int i = 0; i < 4; i++)
#pragma unroll
            for (int j = 0; j < 4; j++) s[i][j] = 0.f;
        for (int d = 0; d < 64; d++) {
            float4 qa = *(const float4*)&Qs[d * APITCH + ty * 4];
            float4 kb = *(const float4*)&Ks[d * APITCH + tx * 4];
            float qv[4] = {qa.x, qa.y, qa.z, qa.w};
            float kv[4] = {kb.x, kb.y, kb.z, kb.w};
#pragma unroll
            for (int i = 0; i < 4; i++)
#pragma unroll
                for (int j = 0; j < 4; j++) s[i][j] += qv[i] * kv[j];
        }
        // scale + mask, per-thread row max
#pragma unroll
        for (int i = 0; i < 4; i++) {
            float mx = -3.0e38f;
#pragma unroll
            for (int j = 0; j < 4; j++) {
                int kg = kt * 64 + tx * 4 + j;
                float v = s[i][j] * 0.125f + ((kg > len) ? -1.0e30f : 0.f);
                s[i][j] = v;
                mx = fmaxf(mx, v);
            }
            red[(ty * 4 + i) * 16 + tx] = mx;
        }
        __syncthreads();

        float mnew[4], scl[4], ps[4];
#pragma unroll
        for (int i = 0; i < 4; i++) {
            int row = ty * 4 + i;
            float mx = mrow[row];
#pragma unroll
            for (int t = 0; t < 16; t++) mx = fmaxf(mx, red[row * 16 + t]);
            mnew[i] = mx;
            scl[i] = __expf(mrow[row] - mx);
            float sum = 0.f;
#pragma unroll
            for (int j = 0; j < 4; j++) {
                float p = __expf(s[i][j] - mx);
                sum += p;
                Ps[(tx * 4 + j) * APITCH + row] = p;
            }
            ps[i] = sum;
#pragma unroll
            for (int j = 0; j < 4; j++) o[i][j] *= scl[i];
        }
        __syncthreads();
#pragma unroll
        for (int i = 0; i < 4; i++) red[(ty * 4 + i) * 16 + tx] = ps[i];
        __syncthreads();
        if (tx == 0) {
#pragma unroll
            for (int i = 0; i < 4; i++) {
                int row = ty * 4 + i;
                float tot = 0.f;
#pragma unroll
                for (int t = 0; t < 16; t++) tot += red[row * 16 + t];
                lrow[row] = lrow[row] * scl[i] + tot;
                mrow[row] = mnew[i];
            }
        }
        // o += P @ V
        for (int kk = 0; kk < 64; kk++) {
            float4 pa = *(const float4*)&Ps[kk * APITCH + ty * 4];
            float4 vb = *(const float4*)&Vs[kk * APITCH + tx * 4];
            float pv[4] = {pa.x, pa.y, pa.z, pa.w};
            float vv[4] = {vb.x, vb.y, vb.z, vb.w};
#pragma unroll
            for (int i = 0; i < 4; i++)
#pragma unroll
                for (int j = 0; j < 4; j++) o[i][j] += pv[i] * vv[j];
        }
        __syncthreads();
    }

#pragma unroll
    for (int i = 0; i < 4; i++) {
        int row = ty * 4 + i;
        float inv = 1.f / lrow[row];
        int q = qt * 64 + row;
#pragma unroll
        for (int j = 0; j < 4; j++)
            ctx[((size_t)(b * S + q)) * D_ + h * 64 + tx * 4 + j] = o[i][j] * inv;
    }
}

// ---------------- layernorm (in place, D=512) -------------------------------
__global__ __launch_bounds__(128) void ln_k(float* __restrict__ x,
                                            const float* __restrict__ g,
                                            const float* __restrict__ bt)
{
    __shared__ float sm8[8];
    int row = blockIdx.x, tid = threadIdx.x;
    float4* xr = (float4*)(x + (size_t)row * D_);
    float4 v = xr[tid];
    float s = v.x + v.y + v.z + v.w;
#pragma unroll
    for (int o = 16; o; o >>= 1) s += __shfl_xor_sync(0xffffffffu, s, o);
    if ((tid & 31) == 0) sm8[tid >> 5] = s;
    __syncthreads();
    float mean = (sm8[0] + sm8[1] + sm8[2] + sm8[3]) * (1.f / (float)D_);
    float d0 = v.x - mean, d1 = v.y - mean, d2 = v.z - mean, d3 = v.w - mean;
    float q = d0 * d0 + d1 * d1 + d2 * d2 + d3 * d3;
#pragma unroll
    for (int o = 16; o; o >>= 1) q += __shfl_xor_sync(0xffffffffu, q, o);
    if ((tid & 31) == 0) sm8[4 + (tid >> 5)] = q;
    __syncthreads();
    float var = (sm8[4] + sm8[5] + sm8[6] + sm8[7]) * (1.f / (float)D_);
    float inv = rsqrtf(var + 1e-5f);
    float4 g4 = ((const float4*)g)[tid];
    float4 b4 = ((const float4*)bt)[tid];
    v.x = d0 * inv * g4.x + b4.x;
    v.y = d1 * inv * g4.y + b4.y;
    v.z = d2 * inv * g4.z + b4.z;
    v.w = d3 * inv * g4.w + b4.w;
    xr[tid] = v;
}

// ---------------- length regulator ------------------------------------------
__global__ void regidx_k(const int* __restrict__ dur, int* __restrict__ idx)
{
    __shared__ int cums[T_];
    int b = blockIdx.x, tid = threadIdx.x;
    cums[tid] = dur[b * T_ + tid];
    __syncthreads();
    if (tid == 0) {
        int a = 0;
        for (int t = 0; t < T_; t++) { a += cums[t]; cums[t] = a; }
    }
    __syncthreads();
    for (int f = tid; f < MEL_; f += T_) {
        int lo = 0, hi = T_;
        while (lo < hi) {
            int mid = (lo + hi) >> 1;
            if (cums[mid] <= f) lo = mid + 1; else hi = mid;
        }
        idx[b * MEL_ + f] = (lo > T_ - 1) ? (T_ - 1) : lo;
    }
}

__global__ void gather_k(const float* __restrict__ enc, const int* __restrict__ idx,
                         const int* __restrict__ mlen, float* __restrict__ out)
{
    int row = blockIdx.x;            // b*MEL + f
    int b = row >> 10, f = row & 1023;
    float keep = (f <= mlen[b]) ? 1.f : 0.f;
    int t = idx[row];
    int tid = threadIdx.x;
    float4 v = ((const float4*)(enc + (size_t)(b * T_ + t) * D_))[tid];
    v.x *= keep; v.y *= keep; v.z *= keep; v.w *= keep;
    ((float4*)(out + (size_t)row * D_))[tid] = v;
}

// ---------------- driver -----------------------------------------------------
extern "C" void kernel_launch(void* const* d_in, const int* in_sizes, int n_in,
                              void* d_out, int out_size)
{
    const int* tokens = (const int*)d_in[0];
    const int* tlen   = (const int*)d_in[1];
    const int* mlen   = (const int*)d_in[2];
    const int* dur    = (const int*)d_in[3];

    int ei = n_in - 27;                       // emb index (robust to scalar mel_len)
    if (ei < 0 || in_sizes[ei] != 256 * D_) {
        for (int i = 0; i < n_in; i++)
            if (in_sizes[i] == 256 * D_) { ei = i; break; }
    }
    const float* emb = (const float*)d_in[ei];
    const float* P[26];
    for (int i = 0; i < 26; i++) P[i] = (const float*)d_in[ei + 1 + i];

    float *gx, *gy, *gctx, *gqkv, *gh;
    int* gidx;
    cudaGetSymbolAddress((void**)&gx,   g_x);
    cudaGetSymbolAddress((void**)&gy,   g_y);
    cudaGetSymbolAddress((void**)&gctx, g_ctx);
    cudaGetSymbolAddress((void**)&gqkv, g_qkv);
    cudaGetSymbolAddress((void**)&gh,   g_h);
    cudaGetSymbolAddress((void**)&gidx, g_idx);

    cudaFuncSetAttribute(attn_k, cudaFuncAttributeMaxDynamicSharedMemorySize,
                         ATTN_SMEM_BYTES);

    embed_k<<<B_ * T_, 128>>>(tokens, emb, gx);

    auto runLayer = [&](const float* const* W, int l, float* x, float* y,
                        int S, const int* lens) {
        int N = B_ * S;
        const float* wqkv = W[0]  + (size_t)l * D_ * 3 * D_;
        const float* bqkv = W[1]  + (size_t)l * 3 * D_;
        const float* wo   = W[2]  + (size_t)l * D_ * D_;
        const float* bo   = W[3]  + (size_t)l * D_;
        const float* l1g  = W[4]  + (size_t)l * D_;
        const float* l1b  = W[5]  + (size_t)l * D_;
        const float* c1w  = W[6]  + (size_t)l * 3 * D_ * INTER_;
        const float* c1b  = W[7]  + (size_t)l * INTER_;
        const float* c2w  = W[8]  + (size_t)l * 3 * INTER_ * D_;
        const float* c2b  = W[9]  + (size_t)l * D_;
        const float* l2g  = W[10] + (size_t)l * D_;
        const float* l2b  = W[11] + (size_t)l * D_;

        gemm_k<0, false, false, false><<<dim3(12, N / 128), 256>>>(
            x, wqkv, bqkv, nullptr, gqkv, N, 3 * D_, D_, S, D_);
        attn_k<<<dim3(S / 64, B_ * H_), 256, ATTN_SMEM_BYTES>>>(gqkv, lens, gctx, S);
        gemm_k<0, false, true, false><<<dim3(4, N / 128), 256>>>(
            gctx, wo, bo, x, y, N, D_, D_, S, D_);
        ln_k<<<N, 128>>>(y, l1g, l1b);
        gemm_k<1, true, false, false><<<dim3(16, N / 128), 256>>>(
            y, c1w, c1b, nullptr, gh, N, INTER_, 3 * D_, S, D_);
        gemm_k<1, false, true, false><<<dim3(4, N / 128), 256>>>(
            gh, c2w, c2b, y, x, N, D_, 3 * INTER_, S, INTER_);
        ln_k<<<N, 128>>>(x, l2g, l2b);
    };

    for (int l = 0; l < L_; l++) runLayer(P, l, gx, gy, T_, tlen);

    regidx_k<<<B_, T_>>>(dur, gidx);
    gather_k<<<B_ * MEL_, 128>>>(gx, gidx, mlen, gy);

    for (int l = 0; l < L_; l++) runLayer(P + 12, l, gy, gx, MEL_, mlen);

    gemm_k<0, false, false, true><<<dim3(1, (B_ * MEL_) / 128), 256>>>(
        gy, P[24], P[25], nullptr, (float*)d_out, B_ * MEL_, OUT_, D_, MEL_, D_);
}

// round 2
// speedup vs baseline: 1.9179x; 1.9179x over previous
#include <cuda_runtime.h>
#include <cstdint>

#define B_    16
#define T_    256
#define MEL_  1024
#define D_    512
#define H_    8
#define L_    4
#define INTER_ 2048
#define OUT_  80

// ---------------- scratch (static device globals: no allocations) ----------
__device__ float g_x  [(size_t)B_*MEL_*D_];
__device__ float g_y  [(size_t)B_*MEL_*D_];
__device__ float g_ctx[(size_t)B_*MEL_*D_];
__device__ float g_qkv[(size_t)B_*MEL_*3*D_];
__device__ float g_h  [(size_t)B_*MEL_*INTER_];
__device__ int   g_idx[B_*MEL_];

__device__ __forceinline__ unsigned f2tf(float x)
{
    unsigned u;
    asm("cvt.rna.tf32.f32 %0, %1;" : "=r"(u) : "f"(x));
    return u;
}

// ---------------- embedding + positional encoding --------------------------
__global__ void embed_k(const int* __restrict__ tokens,
                        const float* __restrict__ emb,
                        float* __restrict__ x)
{
    int row = blockIdx.x;            // b*T + t
    int b   = row >> 8;              // T_=256
    int tok = tokens[row];
    int tid = threadIdx.x;           // 128 threads, float4 each
    float4 e = ((const float4*)(emb + (size_t)tok * D_))[tid];
    int d0 = tid * 4;
    const float c = 9.210340371976184f / (float)D_;   // ln(10000)/D
    float den0 = __expf(-(float)(d0)     * c);
    float den1 = __expf(-(float)(d0 + 2) * c);
    float a0 = (float)b * den0, a1 = (float)b * den1;
    float4 o;
    o.x = 2.f * e.x + sinf(a0);
    o.y = 2.f * e.y + cosf(a0);
    o.z = 2.f * e.z + sinf(a1);
    o.w = 2.f * e.w + cosf(a1);
    ((float4*)(x + (size_t)row * D_))[tid] = o;
}

// ---------------- TF32 tensor-core GEMM  C = op(A) @ W + bias (+R) ---------
// 128x128 CTA tile, BK=16, 8 warps each 32x64, m16n8k8 tf32 HMMA.
// CONV==1: A is [B*S, Din], virtual K dim = 3*Din with SAME zero padding.
// TRANS==1: store C[row,col] at out[(b*OUT_+col)*MEL_ + f]  (row = b*MEL_+f)
#define APIT 20
#define BPIT 136

template<int CONV, bool RELU, bool RESID, bool TRANS>
__global__ __launch_bounds__(256) void gemm_tc(
    const float* __restrict__ A, const float* __restrict__ W,
    const float* __restrict__ bias, const float* __restrict__ R,
    float* __restrict__ C, int N, int M, int Kd, int S, int Din)
{
    __shared__ unsigned As[2][128 * APIT];
    __shared__ unsigned Bs[2][16 * BPIT];

    int tid  = threadIdx.x;
    int lane = tid & 31, warp = tid >> 5;
    int wm = warp & 3, wn = warp >> 2;        // warp tile: rows wm*32, cols wn*64
    int gr = lane >> 2, tig = lane & 3;
    int rowB = blockIdx.y * 128, colB = blockIdx.x * 128;

    float acc[2][8][4];
#pragma unroll
    for (int i = 0; i < 2; i++)
#pragma unroll
        for (int j = 0; j < 8; j++)
#pragma unroll
            for (int q = 0; q < 4; q++) acc[i][j][q] = 0.f;

    float4 aS[2], bS[2];

    auto ldgA = [&](int k0) {
#pragma unroll
        for (int i = 0; i < 2; i++) {
            int u  = tid + i * 256;
            int r  = rowB + (u >> 2);
            int kk = k0 + (u & 3) * 4;
            float4 v = make_float4(0.f, 0.f, 0.f, 0.f);
            if (CONV == 0) {
                v = *(const float4*)(A + (size_t)r * Kd + kk);
            } else {
                int bb = r / S, ss = r - bb * S;
                int kc = kk / Din, d = kk - kc * Din;
                int p  = ss + kc - 1;
                if (p >= 0 && p < S)
                    v = *(const float4*)(A + (size_t)(bb * S + p) * Din + d);
            }
            aS[i] = v;
        }
    };
    auto ldgB = [&](int k0) {
#pragma unroll
        for (int i = 0; i < 2; i++) {
            int u   = tid + i * 256;
            int kr  = u >> 5;                 // 0..15
            int nc  = (u & 31) * 4;
            int col = colB + nc;
            float4 v = make_float4(0.f, 0.f, 0.f, 0.f);
            if (col < M)                       // M % 4 == 0 always here
                v = *(const float4*)(W + (size_t)(k0 + kr) * M + col);
            bS[i] = v;
        }
    };
    auto sts = [&](int s) {
#pragma unroll
        for (int i = 0; i < 2; i++) {
            int u = tid + i * 256;
            int r = u >> 2, ch = u & 3;
            uint4 ta;
            ta.x = f2tf(aS[i].x); ta.y = f2tf(aS[i].y);
            ta.z = f2tf(aS[i].z); ta.w = f2tf(aS[i].w);
            *(uint4*)&As[s][r * APIT + ch * 4] = ta;
            int kr = u >> 5, nc = (u & 31) * 4;
            uint4 tb;
            tb.x = f2tf(bS[i].x); tb.y = f2tf(bS[i].y);
            tb.z = f2tf(bS[i].z); tb.w = f2tf(bS[i].w);
            *(uint4*)&Bs[s][kr * BPIT + nc] = tb;
        }
    };
    auto compute = [&](int s) {
#pragma unroll
        for (int ks = 0; ks < 2; ks++) {
            int kb = ks * 8;
            unsigned af[2][4], bf[8][2];
#pragma unroll
            for (int mi = 0; mi < 2; mi++) {
                int m = wm * 32 + mi * 16 + gr;
                af[mi][0] = As[s][m * APIT + kb + tig];
                af[mi][1] = As[s][(m + 8) * APIT + kb + tig];
                af[mi][2] = As[s][m * APIT + kb + tig + 4];
                af[mi][3] = As[s][(m + 8) * APIT + kb + tig + 4];
            }
#pragma unroll
            for (int ni = 0; ni < 8; ni++) {
                int n = wn * 64 + ni * 8 + gr;
                bf[ni][0] = Bs[s][(kb + tig) * BPIT + n];
                bf[ni][1] = Bs[s][(kb + tig + 4) * BPIT + n];
            }
#pragma unroll
            for (int mi = 0; mi < 2; mi++)
#pragma unroll
                for (int ni = 0; ni < 8; ni++)
                    asm volatile(
                        "mma.sync.aligned.m16n8k8.row.col.f32.tf32.tf32.f32 "
                        "{%0,%1,%2,%3}, {%4,%5,%6,%7}, {%8,%9}, {%0,%1,%2,%3};"
                        : "+f"(acc[mi][ni][0]), "+f"(acc[mi][ni][1]),
                          "+f"(acc[mi][ni][2]), "+f"(acc[mi][ni][3])
                        : "r"(af[mi][0]), "r"(af[mi][1]),
                          "r"(af[mi][2]), "r"(af[mi][3]),
                          "r"(bf[ni][0]), "r"(bf[ni][1]));
        }
    };

    ldgA(0); ldgB(0);
    int s = 0;
    for (int k0 = 0; k0 < Kd; k0 += 16) {
        sts(s);
        __syncthreads();
        if (k0 + 16 < Kd) { ldgA(k0 + 16); ldgB(k0 + 16); }
        compute(s);
        s ^= 1;
    }

#pragma unroll
    for (int mi = 0; mi < 2; mi++) {
        int r0 = rowB + wm * 32 + mi * 16 + gr;
#pragma unroll
        for (int ni = 0; ni < 8; ni++) {
            int c0 = colB + wn * 64 + ni * 8 + tig * 2;
#pragma unroll
            for (int hh = 0; hh < 2; hh++) {
                int r = r0 + hh * 8;
#pragma unroll
                for (int cc = 0; cc < 2; cc++) {
                    int col = c0 + cc;
                    if (col >= M) continue;
                    float v = acc[mi][ni][hh * 2 + cc] + bias[col];
                    if (RESID) v += R[(size_t)r * M + col];
                    if (RELU)  v = fmaxf(v, 0.f);
                    if (!TRANS) {
                        C[(size_t)r * M + col] = v;
                    } else {
                        int bb = r >> 10, f = r & 1023;
                        C[((size_t)(bb * OUT_ + col)) * MEL_ + f] = v;
                    }
                }
            }
        }
    }
}

// ---------------- fused attention (online softmax, 64x64 tiles) ------------
#define APITCH 68
#define ATTN_SMEM_BYTES ((4 * 64 * APITCH + 64 * 16 + 128) * 4)
__global__ __launch_bounds__(256) void attn_k(const float* __restrict__ qkv,
                                              const int* __restrict__ lens,
                                              float* __restrict__ ctx, int S)
{
    extern __shared__ float sm[];
    float* Qs   = sm;                    // [d][q]  pitch 68
    float* Ks   = Qs + 64 * APITCH;      // [d][k]
    float* Vs   = Ks + 64 * APITCH;      // [k][d]
    float* Ps   = Vs + 64 * APITCH;      // [k][q]
    float* red  = Ps + 64 * APITCH;      // [64][16]
    float* mrow = red + 64 * 16;         // [64]
    float* lrow = mrow + 64;             // [64]

    int tid = threadIdx.x;
    int ty = tid >> 4, tx = tid & 15;
    int bh = blockIdx.y;
    int b = bh >> 3, h = bh & 7;
    int qt = blockIdx.x;
    int len = lens[b];
    const float* base = qkv + ((size_t)b * S) * (3 * D_);

#pragma unroll
    for (int r = 0; r < 16; r++) {
        int e = r * 256 + tid;
        int qq = e >> 6, d = e & 63;
        Qs[d * APITCH + qq] = base[(size_t)(qt * 64 + qq) * (3 * D_) + h * 64 + d];
    }
    if (tid < 64) { mrow[tid] = -3.0e38f; lrow[tid] = 0.f; }
    float o[4][4];
#pragma unroll
    for (int i = 0; i < 4; i++)
#pragma unroll
        for (int j = 0; j < 4; j++) o[i][j] = 0.f;
    __syncthreads();

    int nkt = S >> 6;
    for (int kt = 0; kt < nkt; kt++) {
#pragma unroll
        for (int r = 0; r < 16; r++) {
            int e = r * 256 + tid;
            int kk = e >> 6, d = e & 63;
            size_t g = (size_t)(kt * 64 + kk) * (3 * D_) + h * 64 + d;
            Ks[d * APITCH + kk] = base[g + D_];
            Vs[kk * APITCH + d] = base[g + 2 * D_];
        }
        __syncthreads();

        float s[4][4];
#pragma unroll
        for (int i = 0; i < 4; i++)
#pragma unroll
            for (int j = 0; j < 4; j++) s[i][j] = 0.f;
        for (int d = 0; d < 64; d++) {
            float4 qa = *(const float4*)&Qs[d * APITCH + ty * 4];
            float4 kb = *(const float4*)&Ks[d * APITCH + tx * 4];
            float qv[4] = {qa.x, qa.y, qa.z, qa.w};
            float kv[4] = {kb.x, kb.y, kb.z, kb.w};
#pragma unroll
            for (int i = 0; i < 4; i++)
#pragma unroll
                for (int j = 0; j < 4; j++) s[i][j] += qv[i] * kv[j];
        }
#pragma unroll
        for (int i = 0; i < 4; i++) {
            float mx = -3.0e38f;
#pragma unroll
            for (int j = 0; j < 4; j++) {
                int kg = kt * 64 + tx * 4 + j;
                float v = s[i][j] * 0.125f + ((kg > len) ? -1.0e30f : 0.f);
                s[i][j] = v;
                mx = fmaxf(mx, v);
            }
            red[(ty * 4 + i) * 16 + tx] = mx;
        }
        __syncthreads();

        float mnew[4], scl[4], ps[4];
#pragma unroll
        for (int i = 0; i < 4; i++) {
            int row = ty * 4 + i;
            float mx = mrow[row];
#pragma unroll
            for (int t = 0; t < 16; t++) mx = fmaxf(mx, red[row * 16 + t]);
            mnew[i] = mx;
            scl[i] = __expf(mrow[row] - mx);
            float sum = 0.f;
#pragma unroll
            for (int j = 0; j < 4; j++) {
                float p = __expf(s[i][j] - mx);
                sum += p;
                Ps[(tx * 4 + j) * APITCH + row] = p;
            }
            ps[i] = sum;
#pragma unroll
            for (int j = 0; j < 4; j++) o[i][j] *= scl[i];
        }
        __syncthreads();
#pragma unroll
        for (int i = 0; i < 4; i++) red[(ty * 4 + i) * 16 + tx] = ps[i];
        __syncthreads();
        if (tx == 0) {
#pragma unroll
            for (int i = 0; i < 4; i++) {
                int row = ty * 4 + i;
                float tot = 0.f;
#pragma unroll
                for (int t = 0; t < 16; t++) tot += red[row * 16 + t];
                lrow[row] = lrow[row] * scl[i] + tot;
                mrow[row] = mnew[i];
            }
        }
        for (int kk = 0; kk < 64; kk++) {
            float4 pa = *(const float4*)&Ps[kk * APITCH + ty * 4];
            float4 vb = *(const float4*)&Vs[kk * APITCH + tx * 4];
            float pv[4] = {pa.x, pa.y, pa.z, pa.w};
            float vv[4] = {vb.x, vb.y, vb.z, vb.w};
#pragma unroll
            for (int i = 0; i < 4; i++)
#pragma unroll
                for (int j = 0; j < 4; j++) o[i][j] += pv[i] * vv[j];
        }
        __syncthreads();
    }

#pragma unroll
    for (int i = 0; i < 4; i++) {
        int row = ty * 4 + i;
        float inv = 1.f / lrow[row];
        int q = qt * 64 + row;
#pragma unroll
        for (int j = 0; j < 4; j++)
            ctx[((size_t)(b * S + q)) * D_ + h * 64 + tx * 4 + j] = o[i][j] * inv;
    }
}

// ---------------- layernorm (in place, D=512) -------------------------------
__global__ __launch_bounds__(128) void ln_k(float* __restrict__ x,
                                            const float* __restrict__ g,
                                            const float* __restrict__ bt)
{
    __shared__ float sm8[8];
    int row = blockIdx.x, tid = threadIdx.x;
    float4* xr = (float4*)(x + (size_t)row * D_);
    float4 v = xr[tid];
    float s = v.x + v.y + v.z + v.w;
#pragma unroll
    for (int o = 16; o; o >>= 1) s += __shfl_xor_sync(0xffffffffu, s, o);
    if ((tid & 31) == 0) sm8[tid >> 5] = s;
    __syncthreads();
    float mean = (sm8[0] + sm8[1] + sm8[2] + sm8[3]) * (1.f / (float)D_);
    float d0 = v.x - mean, d1 = v.y - mean, d2 = v.z - mean, d3 = v.w - mean;
    float q = d0 * d0 + d1 * d1 + d2 * d2 + d3 * d3;
#pragma unroll
    for (int o = 16; o; o >>= 1) q += __shfl_xor_sync(0xffffffffu, q, o);
    if ((tid & 31) == 0) sm8[4 + (tid >> 5)] = q;
    __syncthreads();
    float var = (sm8[4] + sm8[5] + sm8[6] + sm8[7]) * (1.f / (float)D_);
    float inv = rsqrtf(var + 1e-5f);
    float4 g4 = ((const float4*)g)[tid];
    float4 b4 = ((const float4*)bt)[tid];
    v.x = d0 * inv * g4.x + b4.x;
    v.y = d1 * inv * g4.y + b4.y;
    v.z = d2 * inv * g4.z + b4.z;
    v.w = d3 * inv * g4.w + b4.w;
    xr[tid] = v;
}

// ---------------- length regulator ------------------------------------------
__global__ void regidx_k(const int* __restrict__ dur, int* __restrict__ idx)
{
    __shared__ int cums[T_];
    int b = blockIdx.x, tid = threadIdx.x;
    cums[tid] = dur[b * T_ + tid];
    __syncthreads();
    if (tid == 0) {
        int a = 0;
        for (int t = 0; t < T_; t++) { a += cums[t]; cums[t] = a; }
    }
    __syncthreads();
    for (int f = tid; f < MEL_; f += T_) {
        int lo = 0, hi = T_;
        while (lo < hi) {
            int mid = (lo + hi) >> 1;
            if (cums[mid] <= f) lo = mid + 1; else hi = mid;
        }
        idx[b * MEL_ + f] = (lo > T_ - 1) ? (T_ - 1) : lo;
    }
}

__global__ void gather_k(const float* __restrict__ enc, const int* __restrict__ idx,
                         const int* __restrict__ mlen, float* __restrict__ out)
{
    int row = blockIdx.x;            // b*MEL + f
    int b = row >> 10, f = row & 1023;
    float keep = (f <= mlen[b]) ? 1.f : 0.f;
    int t = idx[row];
    int tid = threadIdx.x;
    float4 v = ((const float4*)(enc + (size_t)(b * T_ + t) * D_))[tid];
    v.x *= keep; v.y *= keep; v.z *= keep; v.w *= keep;
    ((float4*)(out + (size_t)row * D_))[tid] = v;
}

// ---------------- driver -----------------------------------------------------
extern "C" void kernel_launch(void* const* d_in, const int* in_sizes, int n_in,
                              void* d_out, int out_size)
{
    const int* tokens = (const int*)d_in[0];
    const int* tlen   = (const int*)d_in[1];
    const int* mlen   = (const int*)d_in[2];
    const int* dur    = (const int*)d_in[3];

    int ei = n_in - 27;                       // emb index (robust to scalar mel_len)
    if (ei < 0 || in_sizes[ei] != 256 * D_) {
        for (int i = 0; i < n_in; i++)
            if (in_sizes[i] == 256 * D_) { ei = i; break; }
    }
    const float* emb = (const float*)d_in[ei];
    const float* P[26];
    for (int i = 0; i < 26; i++) P[i] = (const float*)d_in[ei + 1 + i];

    float *gx, *gy, *gctx, *gqkv, *gh;
    int* gidx;
    cudaGetSymbolAddress((void**)&gx,   g_x);
    cudaGetSymbolAddress((void**)&gy,   g_y);
    cudaGetSymbolAddress((void**)&gctx, g_ctx);
    cudaGetSymbolAddress((void**)&gqkv, g_qkv);
    cudaGetSymbolAddress((void**)&gh,   g_h);
    cudaGetSymbolAddress((void**)&gidx, g_idx);

    cudaFuncSetAttribute(attn_k, cudaFuncAttributeMaxDynamicSharedMemorySize,
                         ATTN_SMEM_BYTES);

    embed_k<<<B_ * T_, 128>>>(tokens, emb, gx);

    auto runLayer = [&](const float* const* W, int l, float* x, float* y,
                        int S, const int* lens) {
        int N = B_ * S;
        const float* wqkv = W[0]  + (size_t)l * D_ * 3 * D_;
        const float* bqkv = W[1]  + (size_t)l * 3 * D_;
        const float* wo   = W[2]  + (size_t)l * D_ * D_;
        const float* bo   = W[3]  + (size_t)l * D_;
        const float* l1g  = W[4]  + (size_t)l * D_;
        const float* l1b  = W[5]  + (size_t)l * D_;
        const float* c1w  = W[6]  + (size_t)l * 3 * D_ * INTER_;
        const float* c1b  = W[7]  + (size_t)l * INTER_;
        const float* c2w  = W[8]  + (size_t)l * 3 * INTER_ * D_;
        const float* c2b  = W[9]  + (size_t)l * D_;
        const float* l2g  = W[10] + (size_t)l * D_;
        const float* l2b  = W[11] + (size_t)l * D_;

        gemm_tc<0, false, false, false><<<dim3(12, N / 128), 256>>>(
            x, wqkv, bqkv, nullptr, gqkv, N, 3 * D_, D_, S, D_);
        attn_k<<<dim3(S / 64, B_ * H_), 256, ATTN_SMEM_BYTES>>>(gqkv, lens, gctx, S);
        gemm_tc<0, false, true, false><<<dim3(4, N / 128), 256>>>(
            gctx, wo, bo, x, y, N, D_, D_, S, D_);
        ln_k<<<N, 128>>>(y, l1g, l1b);
        gemm_tc<1, true, false, false><<<dim3(16, N / 128), 256>>>(
            y, c1w, c1b, nullptr, gh, N, INTER_, 3 * D_, S, D_);
        gemm_tc<1, false, true, false><<<dim3(4, N / 128), 256>>>(
            gh, c2w, c2b, y, x, N, D_, 3 * INTER_, S, INTER_);
        ln_k<<<N, 128>>>(x, l2g, l2b);
    };

    for (int l = 0; l < L_; l++) runLayer(P, l, gx, gy, T_, tlen);

    regidx_k<<<B_, T_>>>(dur, gidx);
    gather_k<<<B_ * MEL_, 128>>>(gx, gidx, mlen, gy);

    for (int l = 0; l < L_; l++) runLayer(P + 12, l, gy, gx, MEL_, mlen);

    gemm_tc<0, false, false, true><<<dim3(1, (B_ * MEL_) / 128), 256>>>(
        gy, P[24], P[25], nullptr, (float*)d_out, B_ * MEL_, OUT_, D_, MEL_, D_);
}